// round 14
// baseline (speedup 1.0000x reference)
#include <cuda_runtime.h>
#include <cuda_bf16.h>
#include <math.h>
#include <stdint.h>

#define FIN 256
#define HID2 128
#define HH  64
#define NMAX 50000
#define EMAX 800000
#define ENMAX (EMAX + NMAX)

__device__ __align__(16) float g_h1  [NMAX * HID2];
__device__ __align__(16) float g_h2  [NMAX * HH];
__device__ __align__(8) float g_asrc1[NMAX * 2], g_adst1[NMAX * 2];
__device__ float g_asrc2[NMAX], g_adst2[NMAX];
__device__ float g_sum[FIN], g_sumsq[FIN];
__device__ float g_scale[FIN], g_shift[FIN];
__device__ float g_c1[HID2];
// bf16 split operands
__device__ __align__(16) __nv_bfloat16 g_xhi[NMAX * FIN],  g_xlo[NMAX * FIN];
__device__ __align__(16) __nv_bfloat16 g_o1hi[NMAX * HID2], g_o1lo[NMAX * HID2];
__device__ __align__(16) __nv_bfloat16 g_W1t_hi[HID2 * FIN], g_W1t_lo[HID2 * FIN]; // [N][K]
__device__ __align__(16) __nv_bfloat16 g_W2t_hi[HH * HID2],  g_W2t_lo[HH * HID2];  // [N][K]
// CSR
__device__ int g_cnt[NMAX];
__device__ int g_offs[NMAX + 1];
__device__ int g_cursor[NMAX];
__device__ int g_csr[ENMAX];
__device__ int g_bsum[256];
__device__ unsigned g_ctr;

__device__ __forceinline__ float lrelu(float x) { return x > 0.f ? x : 0.2f * x; }
__device__ __forceinline__ float eluf(float x)  { return x > 0.f ? x : expm1f(x); }

__device__ __forceinline__ void split_bf(float v, __nv_bfloat16& h, __nv_bfloat16& l) {
    h = __float2bfloat16_rn(v);
    l = __float2bfloat16_rn(v - __bfloat162float(h));
}

__device__ __forceinline__ void cpasyncz(uint32_t dst_smem, const void* src, int src_bytes) {
    asm volatile("cp.async.cg.shared.global [%0], [%1], 16, %2;"
                 :: "r"(dst_smem), "l"(src), "r"(src_bytes));
}
__device__ __forceinline__ void cp_commit() {
    asm volatile("cp.async.commit_group;" ::: "memory");
}
__device__ __forceinline__ void cp_wait2() {
    asm volatile("cp.async.wait_group 2;" ::: "memory");
}

__device__ __forceinline__ void mma_bf16(float* d, const uint32_t* a, const uint32_t* b) {
    asm volatile(
        "mma.sync.aligned.m16n8k16.row.col.f32.bf16.bf16.f32 "
        "{%0,%1,%2,%3}, {%4,%5,%6,%7}, {%8,%9}, {%0,%1,%2,%3};"
        : "+f"(d[0]), "+f"(d[1]), "+f"(d[2]), "+f"(d[3])
        : "r"(a[0]), "r"(a[1]), "r"(a[2]), "r"(a[3]), "r"(b[0]), "r"(b[1]));
}

// chain-A init: batchnorm accumulators
__global__ void init_stats() {
    int i = threadIdx.x;
    g_sum[i] = 0.f; g_sumsq[i] = 0.f;
    if (i == 0) g_ctr = 0u;
}
// chain-B init: CSR histogram counters
__global__ void init_cnt(int Nn) {
    int i = blockIdx.x * blockDim.x + threadIdx.x;
    if (i < Nn) g_cnt[i] = 0;
}

// batchnorm stats + fused x -> bf16 hi/lo conversion
__global__ void stats_kernel(const float* __restrict__ x,
                             const float* __restrict__ gamma,
                             const float* __restrict__ beta,
                             int Nn, int rowsPerBlock, int nblocks) {
    int col = threadIdx.x;
    int r0 = blockIdx.x * rowsPerBlock;
    int r1 = min(r0 + rowsPerBlock, Nn);
    float s = 0.f, s2 = 0.f;
    for (int r = r0; r < r1; r++) {
        float v = x[(size_t)r * FIN + col];
        s += v; s2 += v * v;
        __nv_bfloat16 h, l;
        split_bf(v, h, l);
        g_xhi[(size_t)r * FIN + col] = h;
        g_xlo[(size_t)r * FIN + col] = l;
    }
    atomicAdd(&g_sum[col], s);
    atomicAdd(&g_sumsq[col], s2);
    __threadfence();
    __shared__ int lastBlk;
    if (col == 0) lastBlk = (atomicAdd(&g_ctr, 1u) == (unsigned)(nblocks - 1)) ? 1 : 0;
    __syncthreads();
    if (lastBlk) {
        float inv = 1.f / (float)Nn;
        float mu  = g_sum[col] * inv;
        float var = g_sumsq[col] * inv - mu * mu;
        float rs  = rsqrtf(var + 1e-5f);
        float sc  = rs * gamma[col];
        g_scale[col] = sc;
        g_shift[col] = beta[col] - mu * sc;
    }
}

// output-major (coalesced writes): blocks 0-127: W1t. 128: c1. 129+: W2t.
__global__ void prep_weights(const float* __restrict__ W1, const float* __restrict__ W2) {
    int b = blockIdx.x;
    if (b < 128) {
        int j = b * 256 + threadIdx.x;          // over HID2*FIN, n-major
        int n = j / FIN, k = j % FIN;
        float v = g_scale[k] * W1[k * HID2 + n];
        __nv_bfloat16 h, l;
        split_bf(v, h, l);
        g_W1t_hi[j] = h;
        g_W1t_lo[j] = l;
    } else if (b == 128) {
        if (threadIdx.x < HID2) {
            int k = threadIdx.x;
            float s = 0.f;
            for (int f = 0; f < FIN; f++) s += g_shift[f] * W1[f * HID2 + k];
            g_c1[k] = s;
        }
    } else {
        int j = (b - 129) * 256 + threadIdx.x;  // over HH*HID2, n-major
        if (j < HH * HID2) {
            int n = j / HID2, k = j % HID2;
            __nv_bfloat16 h, l;
            split_bf(W2[k * HH + n], h, l);
            g_W2t_hi[j] = h;
            g_W2t_lo[j] = l;
        }
    }
}

// ---------- bf16x3 TC GEMM, 4-stage cp.async pipeline, fused attention --------
// NH = attention heads fused in epilogue (0 = none, 1, 2). Head h covers
// columns [h*64, (h+1)*64). avec_src/avec_dst are length-BN coefficient vectors.
// out_asrc/out_adst[node*NH + h] receive per-row dot products of (biased) C rows.
template <int BM, int BN, int NH>
__global__ void __launch_bounds__(256, 2)
gemm_bf3(int M, int N, int K,
         const __nv_bfloat16* __restrict__ Ahi, const __nv_bfloat16* __restrict__ Alo,
         const __nv_bfloat16* __restrict__ Bhi, const __nv_bfloat16* __restrict__ Blo,
         const float* __restrict__ cbias, float* __restrict__ C,
         const float* __restrict__ avec_src, const float* __restrict__ avec_dst,
         float* __restrict__ out_asrc, float* __restrict__ out_adst) {
    constexpr int ARS = 24;
    constexpr int WM = BM / 2, WN = BN / 4;
    constexpr int AM = WM / 16, AN = WN / 8;
    constexpr int ASL = BM * ARS;
    constexpr int BSL = BN * ARS;
    constexpr int BUFSZ = 2 * ASL + 2 * BSL;

    extern __shared__ __nv_bfloat16 sm[];
    uint32_t smbase = (uint32_t)__cvta_generic_to_shared(sm);
    float* satt = (float*)(sm + 4 * BUFSZ);   // [BM][2*NH] : s,d per head

    const int tid  = threadIdx.x;
    const int wid  = tid >> 5;
    const int lane = tid & 31;
    const int wm   = wid >> 2;
    const int wn   = wid & 3;
    const int row0 = blockIdx.x * BM;
    const int lr   = lane >> 2;
    const int lc   = lane & 3;

    if (NH) {
        for (int i = tid; i < BM * 2 * NH; i += 256) satt[i] = 0.f;
    }

    float acc[AM][AN][4];
#pragma unroll
    for (int i = 0; i < AM; i++)
#pragma unroll
        for (int j = 0; j < AN; j++)
#pragma unroll
            for (int q = 0; q < 4; q++) acc[i][j][q] = 0.f;

    const int ntiles = K / 16;

    auto issue = [&](int t, int buf) {
        int k0 = t * 16;
        uint32_t base = (uint32_t)(buf * BUFSZ);
#pragma unroll
        for (int i = tid; i < 4 * BM; i += 256) {
            int arr = i / (2 * BM);
            int rem = i - arr * 2 * BM;
            int r   = rem >> 1;
            int c8  = (rem & 1) * 8;
            int gr  = row0 + r;
            const __nv_bfloat16* src =
                (arr ? Alo : Ahi) + (size_t)(gr < M ? gr : 0) * K + k0 + c8;
            cpasyncz(smbase + (base + (uint32_t)(arr * ASL + r * ARS + c8)) * 2u,
                     src, gr < M ? 16 : 0);
        }
#pragma unroll
        for (int i = tid; i < 4 * BN; i += 256) {
            int arr = i / (2 * BN);
            int rem = i - arr * 2 * BN;
            int n   = rem >> 1;
            int c8  = (rem & 1) * 8;
            const __nv_bfloat16* src = (arr ? Blo : Bhi) + (size_t)n * K + k0 + c8;
            cpasyncz(smbase + (base + (uint32_t)(2 * ASL + arr * BSL + n * ARS + c8)) * 2u,
                     src, 16);
        }
        cp_commit();
    };

#pragma unroll
    for (int p = 0; p < 3; p++) {
        if (p < ntiles) issue(p, p);
        else cp_commit();
    }

    for (int t = 0; t < ntiles; t++) {
        int buf = t & 3;
        cp_wait2();
        __syncthreads();
        if (t + 3 < ntiles) issue(t + 3, (t + 3) & 3);
        else cp_commit();

        const __nv_bfloat16* Ah = sm + buf * BUFSZ;
        const __nv_bfloat16* Al = Ah + ASL;
        const __nv_bfloat16* Bh = Ah + 2 * ASL;
        const __nv_bfloat16* Bl = Bh + BSL;

        uint32_t a_h[AM][4], a_l[AM][4];
#pragma unroll
        for (int mi = 0; mi < AM; mi++) {
            int r = wm * WM + mi * 16 + lr;
            int c = 2 * lc;
            a_h[mi][0] = *(const uint32_t*)(Ah + r * ARS + c);
            a_h[mi][1] = *(const uint32_t*)(Ah + (r + 8) * ARS + c);
            a_h[mi][2] = *(const uint32_t*)(Ah + r * ARS + c + 8);
            a_h[mi][3] = *(const uint32_t*)(Ah + (r + 8) * ARS + c + 8);
            a_l[mi][0] = *(const uint32_t*)(Al + r * ARS + c);
            a_l[mi][1] = *(const uint32_t*)(Al + (r + 8) * ARS + c);
            a_l[mi][2] = *(const uint32_t*)(Al + r * ARS + c + 8);
            a_l[mi][3] = *(const uint32_t*)(Al + (r + 8) * ARS + c + 8);
        }
        uint32_t b_h[AN][2], b_l[AN][2];
#pragma unroll
        for (int ni = 0; ni < AN; ni++) {
            int n = wn * WN + ni * 8 + lr;
            int c = 2 * lc;
            b_h[ni][0] = *(const uint32_t*)(Bh + n * ARS + c);
            b_h[ni][1] = *(const uint32_t*)(Bh + n * ARS + c + 8);
            b_l[ni][0] = *(const uint32_t*)(Bl + n * ARS + c);
            b_l[ni][1] = *(const uint32_t*)(Bl + n * ARS + c + 8);
        }
#pragma unroll
        for (int mi = 0; mi < AM; mi++)
#pragma unroll
            for (int ni = 0; ni < AN; ni++) {
                mma_bf16(acc[mi][ni], a_h[mi], b_h[ni]);
                mma_bf16(acc[mi][ni], a_h[mi], b_l[ni]);
                mma_bf16(acc[mi][ni], a_l[mi], b_h[ni]);
            }
        __syncthreads();
    }

    // one warp's WN-col span lies entirely within one 64-col head
    const int head = (NH == 2) ? ((wn * WN) >> 6) : 0;

#pragma unroll
    for (int mi = 0; mi < AM; mi++) {
        float s0 = 0.f, d0 = 0.f, s1 = 0.f, d1 = 0.f;
#pragma unroll
        for (int ni = 0; ni < AN; ni++) {
            int r = row0 + wm * WM + mi * 16 + lr;
            int c = wn * WN + ni * 8 + 2 * lc;
            float b0 = cbias ? cbias[c] : 0.f;
            float b1 = cbias ? cbias[c + 1] : 0.f;
            float v00 = acc[mi][ni][0] + b0, v01 = acc[mi][ni][1] + b1;
            float v10 = acc[mi][ni][2] + b0, v11 = acc[mi][ni][3] + b1;
            if (r < M)
                *(float2*)(C + (size_t)r * N + c) = make_float2(v00, v01);
            if (r + 8 < M)
                *(float2*)(C + (size_t)(r + 8) * N + c) = make_float2(v10, v11);
            if (NH) {
                float as0 = avec_src[c], as1 = avec_src[c + 1];
                float ad0 = avec_dst[c], ad1 = avec_dst[c + 1];
                s0 += v00 * as0 + v01 * as1;
                d0 += v00 * ad0 + v01 * ad1;
                s1 += v10 * as0 + v11 * as1;
                d1 += v10 * ad0 + v11 * ad1;
            }
        }
        if (NH) {
            int rl = wm * WM + mi * 16 + lr;
            atomicAdd(&satt[rl * 2 * NH + head * 2 + 0], s0);
            atomicAdd(&satt[rl * 2 * NH + head * 2 + 1], d0);
            atomicAdd(&satt[(rl + 8) * 2 * NH + head * 2 + 0], s1);
            atomicAdd(&satt[(rl + 8) * 2 * NH + head * 2 + 1], d1);
        }
    }

    if (NH) {
        __syncthreads();
        if (tid < BM) {
            int gr = row0 + tid;
            if (gr < M) {
#pragma unroll
                for (int h = 0; h < NH; h++) {
                    out_asrc[gr * NH + h] = satt[tid * 2 * NH + h * 2 + 0];
                    out_adst[gr * NH + h] = satt[tid * 2 * NH + h * 2 + 1];
                }
            }
        }
    }
}

__global__ void hist_kernel(const int* __restrict__ ei, int E, int Nn) {
    int i = blockIdx.x * blockDim.x + threadIdx.x;
    if (i >= E + Nn) return;
    int dst = i < E ? ei[E + i] : i - E;
    atomicAdd(&g_cnt[dst], 1);
}

__global__ void scanA(int Nn) {
    __shared__ int sh[256];
    int t = threadIdx.x;
    int i = blockIdx.x * 256 + t;
    int v = (i < Nn) ? g_cnt[i] : 0;
    sh[t] = v; __syncthreads();
#pragma unroll
    for (int o = 1; o < 256; o <<= 1) {
        int add = (t >= o) ? sh[t - o] : 0;
        __syncthreads();
        sh[t] += add;
        __syncthreads();
    }
    if (i < Nn) g_offs[i] = sh[t] - v;
    if (t == 255) g_bsum[blockIdx.x] = sh[255];
}

__global__ void scanB(int nb) {
    __shared__ int sh[256];
    int t = threadIdx.x;
    int v = (t < nb) ? g_bsum[t] : 0;
    sh[t] = v; __syncthreads();
#pragma unroll
    for (int o = 1; o < 256; o <<= 1) {
        int add = (t >= o) ? sh[t - o] : 0;
        __syncthreads();
        sh[t] += add;
        __syncthreads();
    }
    g_bsum[t] = sh[t] - v;
}

__global__ void scanC(int Nn, int EN) {
    int i = blockIdx.x * blockDim.x + threadIdx.x;
    if (i < Nn) {
        int o = g_offs[i] + g_bsum[i >> 8];
        g_offs[i] = o;
        g_cursor[i] = o;
    }
    if (i == 0) g_offs[Nn] = EN;
}

__global__ void fill_kernel(const int* __restrict__ ei, int E, int Nn) {
    int i = blockIdx.x * blockDim.x + threadIdx.x;
    if (i >= E + Nn) return;
    int src = i < E ? ei[i] : i - E;
    int dst = i < E ? ei[E + i] : i - E;
    int pos = atomicAdd(&g_cursor[dst], 1);
    g_csr[pos] = src;
}

// gather1: softmax aggregation + elu(.+b1), emit bf16 hi/lo for GEMM2
__global__ void gather1(const float* __restrict__ b1, int Nn) {
    int w    = (blockIdx.x * blockDim.x + threadIdx.x) >> 5;
    int lane = threadIdx.x & 31;
    if (w >= Nn) return;
    int s = g_offs[w], e = g_offs[w + 1];
    float2 ad = *(const float2*)&g_adst1[w * 2];
    float4 acc = make_float4(0.f, 0.f, 0.f, 0.f);
    float d0 = 0.f, d1 = 0.f;
    const float* h1base = g_h1 + lane * 4;
    for (int i = s; i < e; i++) {
        int src = __ldg(&g_csr[i]);
        float2 as = *(const float2*)&g_asrc1[src * 2];
        float e0 = __expf(lrelu(as.x + ad.x));
        float e1 = __expf(lrelu(as.y + ad.y));
        d0 += e0; d1 += e1;
        float al = (lane < 16) ? e0 : e1;
        float4 v = *(const float4*)(h1base + (size_t)src * HID2);
        acc.x += al * v.x; acc.y += al * v.y;
        acc.z += al * v.z; acc.w += al * v.w;
    }
    float rd = (lane < 16) ? (1.f / d0) : (1.f / d1);
    float4 bb = *(const float4*)(b1 + lane * 4);
    float o[4];
    o[0] = eluf(acc.x * rd + bb.x);
    o[1] = eluf(acc.y * rd + bb.y);
    o[2] = eluf(acc.z * rd + bb.z);
    o[3] = eluf(acc.w * rd + bb.w);
    uint32_t hp[2], lp[2];
#pragma unroll
    for (int q = 0; q < 2; q++) {
        __nv_bfloat16 h0, l0, h1b_, l1;
        split_bf(o[2 * q], h0, l0);
        split_bf(o[2 * q + 1], h1b_, l1);
        hp[q] = (uint32_t)__bfloat16_as_ushort(h0) | ((uint32_t)__bfloat16_as_ushort(h1b_) << 16);
        lp[q] = (uint32_t)__bfloat16_as_ushort(l0) | ((uint32_t)__bfloat16_as_ushort(l1) << 16);
    }
    size_t off = (size_t)w * HID2 + lane * 4;
    *(uint2*)(g_o1hi + off) = make_uint2(hp[0], hp[1]);
    *(uint2*)(g_o1lo + off) = make_uint2(lp[0], lp[1]);
}

// gather2 + final MLP fused: softmax aggregation -> +b2 -> MLP -> out
__global__ void gather2_final(const float* __restrict__ b2,
                              const float* __restrict__ Wc1,
                              const float* __restrict__ bc1,
                              const float* __restrict__ Wc2,
                              const float* __restrict__ bc2,
                              float* __restrict__ out, int Nn) {
    __shared__ float sW1[64 * 16], sW2[32], sb1[16], sb2[2], sB2[64];
    int tid = threadIdx.x;
    for (int i = tid; i < 64 * 16; i += blockDim.x) sW1[i] = Wc1[i];
    if (tid < 32) sW2[tid] = Wc2[tid];
    if (tid < 16) sb1[tid] = bc1[tid];
    if (tid < 2)  sb2[tid] = bc2[tid];
    if (tid < 64) sB2[tid] = b2[tid];
    __syncthreads();

    int w    = (blockIdx.x * blockDim.x + tid) >> 5;
    int lane = tid & 31;
    if (w >= Nn) return;
    int s = g_offs[w], e = g_offs[w + 1];
    float ad = g_adst2[w];
    float2 acc = make_float2(0.f, 0.f);
    float d = 0.f;
    const float* h2base = g_h2 + lane * 2;
    for (int i = s; i < e; i++) {
        int src = __ldg(&g_csr[i]);
        float ee = __expf(lrelu(g_asrc2[src] + ad));
        d += ee;
        float2 v = *(const float2*)(h2base + (size_t)src * HH);
        acc.x += ee * v.x; acc.y += ee * v.y;
    }
    float rd = 1.f / d;
    float v0 = acc.x * rd + sB2[lane * 2];
    float v1 = acc.y * rd + sB2[lane * 2 + 1];

    float t[16];
#pragma unroll
    for (int j = 0; j < 16; j++)
        t[j] = v0 * sW1[(lane * 2) * 16 + j] + v1 * sW1[(lane * 2 + 1) * 16 + j];
#pragma unroll
    for (int o = 16; o; o >>= 1)
#pragma unroll
        for (int j = 0; j < 16; j++)
            t[j] += __shfl_down_sync(0xffffffffu, t[j], o);
    if (lane == 0) {
        float o0 = sb2[0], o1 = sb2[1];
#pragma unroll
        for (int j = 0; j < 16; j++) {
            float tj = t[j] + sb1[j];
            tj = tj > 0.f ? tj : 0.f;
            o0 += tj * sW2[j * 2]; o1 += tj * sW2[j * 2 + 1];
        }
        out[w * 2]     = o0;
        out[w * 2 + 1] = o1;
    }
}

extern "C" void kernel_launch(void* const* d_in, const int* in_sizes, int n_in,
                              void* d_out, int out_size) {
    const float* x  = (const float*)d_in[0];
    const int*   ei = (const int*)d_in[1];
    int Nn = in_sizes[0] / FIN;
    int E  = in_sizes[1] / 2;

    int g = -1;
    for (int i = 2; i + 2 < n_in; i++) {
        if (in_sizes[i] == 256 && in_sizes[i + 1] == 256 && in_sizes[i + 2] == FIN * HID2) {
            g = i; break;
        }
    }
    if (g < 0) g = 6;
    const float* gamma  = (const float*)d_in[g + 0];
    const float* beta   = (const float*)d_in[g + 1];
    const float* W1     = (const float*)d_in[g + 2];
    const float* a_src1 = (const float*)d_in[g + 3];
    const float* a_dst1 = (const float*)d_in[g + 4];
    const float* b1     = (const float*)d_in[g + 5];
    const float* W2     = (const float*)d_in[g + 6];
    const float* a_src2 = (const float*)d_in[g + 7];
    const float* a_dst2 = (const float*)d_in[g + 8];
    const float* b2     = (const float*)d_in[g + 9];
    const float* Wc1    = (const float*)d_in[g + 10];
    const float* bc1    = (const float*)d_in[g + 11];
    const float* Wc2    = (const float*)d_in[g + 12];
    const float* bc2    = (const float*)d_in[g + 13];
    float* out = (float*)d_out;

    float *p_h1, *p_h2, *p_c1, *p_as1, *p_ad1, *p_as2, *p_ad2;
    __nv_bfloat16 *p_xhi, *p_xlo, *p_o1hi, *p_o1lo, *p_w1h, *p_w1l, *p_w2h, *p_w2l;
    cudaGetSymbolAddress((void**)&p_h1,   g_h1);
    cudaGetSymbolAddress((void**)&p_h2,   g_h2);
    cudaGetSymbolAddress((void**)&p_c1,   g_c1);
    cudaGetSymbolAddress((void**)&p_as1,  g_asrc1);
    cudaGetSymbolAddress((void**)&p_ad1,  g_adst1);
    cudaGetSymbolAddress((void**)&p_as2,  g_asrc2);
    cudaGetSymbolAddress((void**)&p_ad2,  g_adst2);
    cudaGetSymbolAddress((void**)&p_xhi,  g_xhi);
    cudaGetSymbolAddress((void**)&p_xlo,  g_xlo);
    cudaGetSymbolAddress((void**)&p_o1hi, g_o1hi);
    cudaGetSymbolAddress((void**)&p_o1lo, g_o1lo);
    cudaGetSymbolAddress((void**)&p_w1h,  g_W1t_hi);
    cudaGetSymbolAddress((void**)&p_w1l,  g_W1t_lo);
    cudaGetSymbolAddress((void**)&p_w2h,  g_W2t_hi);
    cudaGetSymbolAddress((void**)&p_w2l,  g_W2t_lo);

    int EN = E + Nn;
    int nScanBlocks = (Nn + 255) / 256;

    // dynamic smem: 4 pipeline buffers + att scratch (BM*2*NH floats)
    constexpr int SMEM1 = 4 * (2 * 128 * 24 + 2 * 128 * 24) * 2 + 128 * 4 * 4;  // 100352
    constexpr int SMEM2 = 4 * (2 * 128 * 24 + 2 * 64 * 24) * 2 + 128 * 2 * 4;   // 74752
    cudaFuncSetAttribute((const void*)gemm_bf3<128, 128, 2>,
                         cudaFuncAttributeMaxDynamicSharedMemorySize, SMEM1);
    cudaFuncSetAttribute((const void*)gemm_bf3<128, 64, 1>,
                         cudaFuncAttributeMaxDynamicSharedMemorySize, SMEM2);

    // one-time side stream + events (created on the uncaptured correctness run)
    static cudaStream_t s2 = nullptr;
    static cudaEvent_t evFork = nullptr, evJoin = nullptr;
    if (s2 == nullptr) {
        cudaStreamCreateWithFlags(&s2, cudaStreamNonBlocking);
        cudaEventCreateWithFlags(&evFork, cudaEventDisableTiming);
        cudaEventCreateWithFlags(&evJoin, cudaEventDisableTiming);
    }

    // ---- fork: CSR chain on s2, dense chain on the launch stream ----
    cudaEventRecord(evFork, 0);
    cudaStreamWaitEvent(s2, evFork, 0);

    // chain B (s2): CSR build
    init_cnt<<<(Nn + 255) / 256, 256, 0, s2>>>(Nn);
    hist_kernel<<<(EN + 255) / 256, 256, 0, s2>>>(ei, E, Nn);
    scanA<<<nScanBlocks, 256, 0, s2>>>(Nn);
    scanB<<<1, 256, 0, s2>>>(nScanBlocks);
    scanC<<<(Nn + 255) / 256, 256, 0, s2>>>(Nn, EN);
    fill_kernel<<<(EN + 255) / 256, 256, 0, s2>>>(ei, E, Nn);
    cudaEventRecord(evJoin, s2);

    // chain A (stream 0): BN-stats -> weights -> GEMM1(+att1 fused)
    init_stats<<<1, 256>>>();
    int rowsPerBlock = 256;
    int nStatBlocks = (Nn + rowsPerBlock - 1) / rowsPerBlock;
    stats_kernel<<<nStatBlocks, 256>>>(x, gamma, beta, Nn, rowsPerBlock, nStatBlocks);
    prep_weights<<<161, 256>>>(W1, W2);
    gemm_bf3<128, 128, 2>
        <<<(Nn + 127) / 128, 256, SMEM1>>>(Nn, HID2, FIN, p_xhi, p_xlo, p_w1h, p_w1l,
                                           p_c1, p_h1, a_src1, a_dst1, p_as1, p_ad1);

    // ---- join: gather1 needs both chains ----
    cudaStreamWaitEvent(0, evJoin, 0);

    gather1<<<((size_t)Nn * 32 + 255) / 256, 256>>>(b1, Nn);
    gemm_bf3<128, 64, 1>
        <<<(Nn + 127) / 128, 256, SMEM2>>>(Nn, HH, HID2, p_o1hi, p_o1lo, p_w2h, p_w2l,
                                           nullptr, p_h2, a_src2, a_dst2, p_as2, p_ad2);
    gather2_final<<<((size_t)Nn * 32 + 255) / 256, 256>>>(b2, Wc1, bc1, Wc2, bc2, out, Nn);
}

// round 15
// speedup vs baseline: 1.2773x; 1.2773x over previous
#include <cuda_runtime.h>
#include <cuda_bf16.h>
#include <math.h>
#include <stdint.h>

#define FIN 256
#define HID2 128
#define HH  64
#define NMAX 50000
#define EMAX 800000
#define ENMAX (EMAX + NMAX)

__device__ __align__(16) float g_h1  [NMAX * HID2];
__device__ __align__(16) float g_h2  [NMAX * HH];
__device__ __align__(16) float g_out2[NMAX * HH];
__device__ __align__(8) float g_asrc1[NMAX * 2], g_adst1[NMAX * 2];
__device__ float g_asrc2[NMAX], g_adst2[NMAX];
__device__ float g_sum[FIN], g_sumsq[FIN];
__device__ float g_scale[FIN], g_shift[FIN];
__device__ float g_c1[HID2];
// bf16 split operands
__device__ __align__(16) __nv_bfloat16 g_xhi[NMAX * FIN],  g_xlo[NMAX * FIN];
__device__ __align__(16) __nv_bfloat16 g_o1hi[NMAX * HID2], g_o1lo[NMAX * HID2];
__device__ __align__(16) __nv_bfloat16 g_W1t_hi[HID2 * FIN], g_W1t_lo[HID2 * FIN]; // [N][K]
__device__ __align__(16) __nv_bfloat16 g_W2t_hi[HH * HID2],  g_W2t_lo[HH * HID2];  // [N][K]
// CSR
__device__ int g_cnt[NMAX];
__device__ int g_offs[NMAX + 1];
__device__ int g_cursor[NMAX];
__device__ int g_csr[ENMAX];
__device__ int g_bsum[256];
__device__ unsigned g_ctr;

__device__ __forceinline__ float lrelu(float x) { return x > 0.f ? x : 0.2f * x; }
__device__ __forceinline__ float eluf(float x)  { return x > 0.f ? x : expm1f(x); }

__device__ __forceinline__ void split_bf(float v, __nv_bfloat16& h, __nv_bfloat16& l) {
    h = __float2bfloat16_rn(v);
    l = __float2bfloat16_rn(v - __bfloat162float(h));
}

__device__ __forceinline__ void cpasyncz(uint32_t dst_smem, const void* src, int src_bytes) {
    asm volatile("cp.async.cg.shared.global [%0], [%1], 16, %2;"
                 :: "r"(dst_smem), "l"(src), "r"(src_bytes));
}
__device__ __forceinline__ void cp_commit() {
    asm volatile("cp.async.commit_group;" ::: "memory");
}
__device__ __forceinline__ void cp_wait2() {
    asm volatile("cp.async.wait_group 2;" ::: "memory");
}

__device__ __forceinline__ void mma_bf16(float* d, const uint32_t* a, const uint32_t* b) {
    asm volatile(
        "mma.sync.aligned.m16n8k16.row.col.f32.bf16.bf16.f32 "
        "{%0,%1,%2,%3}, {%4,%5,%6,%7}, {%8,%9}, {%0,%1,%2,%3};"
        : "+f"(d[0]), "+f"(d[1]), "+f"(d[2]), "+f"(d[3])
        : "r"(a[0]), "r"(a[1]), "r"(a[2]), "r"(a[3]), "r"(b[0]), "r"(b[1]));
}

// chain-A init: batchnorm accumulators
__global__ void init_stats() {
    int i = threadIdx.x;
    g_sum[i] = 0.f; g_sumsq[i] = 0.f;
    if (i == 0) g_ctr = 0u;
}
// chain-B init: CSR histogram counters
__global__ void init_cnt(int Nn) {
    int i = blockIdx.x * blockDim.x + threadIdx.x;
    if (i < Nn) g_cnt[i] = 0;
}

// batchnorm stats + fused x -> bf16 hi/lo conversion
__global__ void stats_kernel(const float* __restrict__ x,
                             const float* __restrict__ gamma,
                             const float* __restrict__ beta,
                             int Nn, int rowsPerBlock, int nblocks) {
    int col = threadIdx.x;
    int r0 = blockIdx.x * rowsPerBlock;
    int r1 = min(r0 + rowsPerBlock, Nn);
    float s = 0.f, s2 = 0.f;
    for (int r = r0; r < r1; r++) {
        float v = x[(size_t)r * FIN + col];
        s += v; s2 += v * v;
        __nv_bfloat16 h, l;
        split_bf(v, h, l);
        g_xhi[(size_t)r * FIN + col] = h;
        g_xlo[(size_t)r * FIN + col] = l;
    }
    atomicAdd(&g_sum[col], s);
    atomicAdd(&g_sumsq[col], s2);
    __threadfence();
    __shared__ int lastBlk;
    if (col == 0) lastBlk = (atomicAdd(&g_ctr, 1u) == (unsigned)(nblocks - 1)) ? 1 : 0;
    __syncthreads();
    if (lastBlk) {
        float inv = 1.f / (float)Nn;
        float mu  = g_sum[col] * inv;
        float var = g_sumsq[col] * inv - mu * mu;
        float rs  = rsqrtf(var + 1e-5f);
        float sc  = rs * gamma[col];
        g_scale[col] = sc;
        g_shift[col] = beta[col] - mu * sc;
    }
}

// output-major (coalesced writes): blocks 0-127: W1t. 128: c1. 129+: W2t.
__global__ void prep_weights(const float* __restrict__ W1, const float* __restrict__ W2) {
    int b = blockIdx.x;
    if (b < 128) {
        int j = b * 256 + threadIdx.x;          // over HID2*FIN, n-major
        int n = j / FIN, k = j % FIN;
        float v = g_scale[k] * W1[k * HID2 + n];
        __nv_bfloat16 h, l;
        split_bf(v, h, l);
        g_W1t_hi[j] = h;
        g_W1t_lo[j] = l;
    } else if (b == 128) {
        if (threadIdx.x < HID2) {
            int k = threadIdx.x;
            float s = 0.f;
            for (int f = 0; f < FIN; f++) s += g_shift[f] * W1[f * HID2 + k];
            g_c1[k] = s;
        }
    } else {
        int j = (b - 129) * 256 + threadIdx.x;  // over HH*HID2, n-major
        if (j < HH * HID2) {
            int n = j / HID2, k = j % HID2;
            __nv_bfloat16 h, l;
            split_bf(W2[k * HH + n], h, l);
            g_W2t_hi[j] = h;
            g_W2t_lo[j] = l;
        }
    }
}

// ---------- bf16x3 TC GEMM, 4-stage cp.async pipeline --------------------------
template <int BM, int BN>
__global__ void __launch_bounds__(256, 2)
gemm_bf3(int M, int N, int K,
         const __nv_bfloat16* __restrict__ Ahi, const __nv_bfloat16* __restrict__ Alo,
         const __nv_bfloat16* __restrict__ Bhi, const __nv_bfloat16* __restrict__ Blo,
         const float* __restrict__ cbias, float* __restrict__ C) {
    constexpr int ARS = 24;
    constexpr int WM = BM / 2, WN = BN / 4;
    constexpr int AM = WM / 16, AN = WN / 8;
    constexpr int ASL = BM * ARS;
    constexpr int BSL = BN * ARS;
    constexpr int BUFSZ = 2 * ASL + 2 * BSL;

    extern __shared__ __nv_bfloat16 sm[];
    uint32_t smbase = (uint32_t)__cvta_generic_to_shared(sm);

    const int tid  = threadIdx.x;
    const int wid  = tid >> 5;
    const int lane = tid & 31;
    const int wm   = wid >> 2;
    const int wn   = wid & 3;
    const int row0 = blockIdx.x * BM;
    const int lr   = lane >> 2;
    const int lc   = lane & 3;

    float acc[AM][AN][4];
#pragma unroll
    for (int i = 0; i < AM; i++)
#pragma unroll
        for (int j = 0; j < AN; j++)
#pragma unroll
            for (int q = 0; q < 4; q++) acc[i][j][q] = 0.f;

    const int ntiles = K / 16;

    auto issue = [&](int t, int buf) {
        int k0 = t * 16;
        uint32_t base = (uint32_t)(buf * BUFSZ);
#pragma unroll
        for (int i = tid; i < 4 * BM; i += 256) {
            int arr = i / (2 * BM);
            int rem = i - arr * 2 * BM;
            int r   = rem >> 1;
            int c8  = (rem & 1) * 8;
            int gr  = row0 + r;
            const __nv_bfloat16* src =
                (arr ? Alo : Ahi) + (size_t)(gr < M ? gr : 0) * K + k0 + c8;
            cpasyncz(smbase + (base + (uint32_t)(arr * ASL + r * ARS + c8)) * 2u,
                     src, gr < M ? 16 : 0);
        }
#pragma unroll
        for (int i = tid; i < 4 * BN; i += 256) {
            int arr = i / (2 * BN);
            int rem = i - arr * 2 * BN;
            int n   = rem >> 1;
            int c8  = (rem & 1) * 8;
            const __nv_bfloat16* src = (arr ? Blo : Bhi) + (size_t)n * K + k0 + c8;
            cpasyncz(smbase + (base + (uint32_t)(2 * ASL + arr * BSL + n * ARS + c8)) * 2u,
                     src, 16);
        }
        cp_commit();
    };

#pragma unroll
    for (int p = 0; p < 3; p++) {
        if (p < ntiles) issue(p, p);
        else cp_commit();
    }

    for (int t = 0; t < ntiles; t++) {
        int buf = t & 3;
        cp_wait2();
        __syncthreads();
        if (t + 3 < ntiles) issue(t + 3, (t + 3) & 3);
        else cp_commit();

        const __nv_bfloat16* Ah = sm + buf * BUFSZ;
        const __nv_bfloat16* Al = Ah + ASL;
        const __nv_bfloat16* Bh = Ah + 2 * ASL;
        const __nv_bfloat16* Bl = Bh + BSL;

        uint32_t a_h[AM][4], a_l[AM][4];
#pragma unroll
        for (int mi = 0; mi < AM; mi++) {
            int r = wm * WM + mi * 16 + lr;
            int c = 2 * lc;
            a_h[mi][0] = *(const uint32_t*)(Ah + r * ARS + c);
            a_h[mi][1] = *(const uint32_t*)(Ah + (r + 8) * ARS + c);
            a_h[mi][2] = *(const uint32_t*)(Ah + r * ARS + c + 8);
            a_h[mi][3] = *(const uint32_t*)(Ah + (r + 8) * ARS + c + 8);
            a_l[mi][0] = *(const uint32_t*)(Al + r * ARS + c);
            a_l[mi][1] = *(const uint32_t*)(Al + (r + 8) * ARS + c);
            a_l[mi][2] = *(const uint32_t*)(Al + r * ARS + c + 8);
            a_l[mi][3] = *(const uint32_t*)(Al + (r + 8) * ARS + c + 8);
        }
        uint32_t b_h[AN][2], b_l[AN][2];
#pragma unroll
        for (int ni = 0; ni < AN; ni++) {
            int n = wn * WN + ni * 8 + lr;
            int c = 2 * lc;
            b_h[ni][0] = *(const uint32_t*)(Bh + n * ARS + c);
            b_h[ni][1] = *(const uint32_t*)(Bh + n * ARS + c + 8);
            b_l[ni][0] = *(const uint32_t*)(Bl + n * ARS + c);
            b_l[ni][1] = *(const uint32_t*)(Bl + n * ARS + c + 8);
        }
#pragma unroll
        for (int mi = 0; mi < AM; mi++)
#pragma unroll
            for (int ni = 0; ni < AN; ni++) {
                mma_bf16(acc[mi][ni], a_h[mi], b_h[ni]);
                mma_bf16(acc[mi][ni], a_h[mi], b_l[ni]);
                mma_bf16(acc[mi][ni], a_l[mi], b_h[ni]);
            }
        __syncthreads();
    }

#pragma unroll
    for (int mi = 0; mi < AM; mi++) {
#pragma unroll
        for (int ni = 0; ni < AN; ni++) {
            int r = row0 + wm * WM + mi * 16 + lr;
            int c = wn * WN + ni * 8 + 2 * lc;
            float b0 = cbias ? cbias[c] : 0.f;
            float b1 = cbias ? cbias[c + 1] : 0.f;
            if (r < M)
                *(float2*)(C + (size_t)r * N + c) =
                    make_float2(acc[mi][ni][0] + b0, acc[mi][ni][1] + b1);
            if (r + 8 < M)
                *(float2*)(C + (size_t)(r + 8) * N + c) =
                    make_float2(acc[mi][ni][2] + b0, acc[mi][ni][3] + b1);
        }
    }
}

__global__ void hist_kernel(const int* __restrict__ ei, int E, int Nn) {
    int i = blockIdx.x * blockDim.x + threadIdx.x;
    if (i >= E + Nn) return;
    int dst = i < E ? ei[E + i] : i - E;
    atomicAdd(&g_cnt[dst], 1);
}

__global__ void scanA(int Nn) {
    __shared__ int sh[256];
    int t = threadIdx.x;
    int i = blockIdx.x * 256 + t;
    int v = (i < Nn) ? g_cnt[i] : 0;
    sh[t] = v; __syncthreads();
#pragma unroll
    for (int o = 1; o < 256; o <<= 1) {
        int add = (t >= o) ? sh[t - o] : 0;
        __syncthreads();
        sh[t] += add;
        __syncthreads();
    }
    if (i < Nn) g_offs[i] = sh[t] - v;
    if (t == 255) g_bsum[blockIdx.x] = sh[255];
}

__global__ void scanB(int nb) {
    __shared__ int sh[256];
    int t = threadIdx.x;
    int v = (t < nb) ? g_bsum[t] : 0;
    sh[t] = v; __syncthreads();
#pragma unroll
    for (int o = 1; o < 256; o <<= 1) {
        int add = (t >= o) ? sh[t - o] : 0;
        __syncthreads();
        sh[t] += add;
        __syncthreads();
    }
    g_bsum[t] = sh[t] - v;
}

__global__ void scanC(int Nn, int EN) {
    int i = blockIdx.x * blockDim.x + threadIdx.x;
    if (i < Nn) {
        int o = g_offs[i] + g_bsum[i >> 8];
        g_offs[i] = o;
        g_cursor[i] = o;
    }
    if (i == 0) g_offs[Nn] = EN;
}

__global__ void fill_kernel(const int* __restrict__ ei, int E, int Nn) {
    int i = blockIdx.x * blockDim.x + threadIdx.x;
    if (i >= E + Nn) return;
    int src = i < E ? ei[i] : i - E;
    int dst = i < E ? ei[E + i] : i - E;
    int pos = atomicAdd(&g_cursor[dst], 1);
    g_csr[pos] = src;
}

__global__ void att1_kernel(const float* __restrict__ a_src,
                            const float* __restrict__ a_dst, int Nn) {
    int gw   = (blockIdx.x * blockDim.x + threadIdx.x) >> 5;
    int lane = threadIdx.x & 31;
    if (gw >= Nn) return;
    const float* row = g_h1 + (size_t)gw * HID2;
    float h0a = row[lane], h0b = row[lane + 32];
    float h1a = row[64 + lane], h1b = row[96 + lane];
    float s0 = h0a * a_src[lane] + h0b * a_src[lane + 32];
    float d0 = h0a * a_dst[lane] + h0b * a_dst[lane + 32];
    float s1 = h1a * a_src[64 + lane] + h1b * a_src[96 + lane];
    float d1 = h1a * a_dst[64 + lane] + h1b * a_dst[96 + lane];
#pragma unroll
    for (int o = 16; o; o >>= 1) {
        s0 += __shfl_down_sync(0xffffffffu, s0, o);
        d0 += __shfl_down_sync(0xffffffffu, d0, o);
        s1 += __shfl_down_sync(0xffffffffu, s1, o);
        d1 += __shfl_down_sync(0xffffffffu, d1, o);
    }
    if (lane == 0) {
        g_asrc1[gw * 2] = s0; g_asrc1[gw * 2 + 1] = s1;
        g_adst1[gw * 2] = d0; g_adst1[gw * 2 + 1] = d1;
    }
}

__global__ void att2_kernel(const float* __restrict__ a_src,
                            const float* __restrict__ a_dst, int Nn) {
    int gw   = (blockIdx.x * blockDim.x + threadIdx.x) >> 5;
    int lane = threadIdx.x & 31;
    if (gw >= Nn) return;
    const float* row = g_h2 + (size_t)gw * HH;
    float ha = row[lane], hb = row[lane + 32];
    float s = ha * a_src[lane] + hb * a_src[lane + 32];
    float d = ha * a_dst[lane] + hb * a_dst[lane + 32];
#pragma unroll
    for (int o = 16; o; o >>= 1) {
        s += __shfl_down_sync(0xffffffffu, s, o);
        d += __shfl_down_sync(0xffffffffu, d, o);
    }
    if (lane == 0) { g_asrc2[gw] = s; g_adst2[gw] = d; }
}

// gather1: softmax aggregation + elu(.+b1), emit bf16 hi/lo for GEMM2
__global__ void gather1(const float* __restrict__ b1, int Nn) {
    int w    = (blockIdx.x * blockDim.x + threadIdx.x) >> 5;
    int lane = threadIdx.x & 31;
    if (w >= Nn) return;
    int s = g_offs[w], e = g_offs[w + 1];
    float2 ad = *(const float2*)&g_adst1[w * 2];
    float4 acc = make_float4(0.f, 0.f, 0.f, 0.f);
    float d0 = 0.f, d1 = 0.f;
    const float* h1base = g_h1 + lane * 4;
    for (int i = s; i < e; i++) {
        int src = __ldg(&g_csr[i]);
        float2 as = *(const float2*)&g_asrc1[src * 2];
        float e0 = __expf(lrelu(as.x + ad.x));
        float e1 = __expf(lrelu(as.y + ad.y));
        d0 += e0; d1 += e1;
        float al = (lane < 16) ? e0 : e1;
        float4 v = *(const float4*)(h1base + (size_t)src * HID2);
        acc.x += al * v.x; acc.y += al * v.y;
        acc.z += al * v.z; acc.w += al * v.w;
    }
    float rd = (lane < 16) ? (1.f / d0) : (1.f / d1);
    float4 bb = *(const float4*)(b1 + lane * 4);
    float o[4];
    o[0] = eluf(acc.x * rd + bb.x);
    o[1] = eluf(acc.y * rd + bb.y);
    o[2] = eluf(acc.z * rd + bb.z);
    o[3] = eluf(acc.w * rd + bb.w);
    uint32_t hp[2], lp[2];
#pragma unroll
    for (int q = 0; q < 2; q++) {
        __nv_bfloat16 h0, l0, h1b_, l1;
        split_bf(o[2 * q], h0, l0);
        split_bf(o[2 * q + 1], h1b_, l1);
        hp[q] = (uint32_t)__bfloat16_as_ushort(h0) | ((uint32_t)__bfloat16_as_ushort(h1b_) << 16);
        lp[q] = (uint32_t)__bfloat16_as_ushort(l0) | ((uint32_t)__bfloat16_as_ushort(l1) << 16);
    }
    size_t off = (size_t)w * HID2 + lane * 4;
    *(uint2*)(g_o1hi + off) = make_uint2(hp[0], hp[1]);
    *(uint2*)(g_o1lo + off) = make_uint2(lp[0], lp[1]);
}

__global__ void gather2(int Nn) {
    int w    = (blockIdx.x * blockDim.x + threadIdx.x) >> 5;
    int lane = threadIdx.x & 31;
    if (w >= Nn) return;
    int s = g_offs[w], e = g_offs[w + 1];
    float ad = g_adst2[w];
    float2 acc = make_float2(0.f, 0.f);
    float d = 0.f;
    const float* h2base = g_h2 + lane * 2;
    for (int i = s; i < e; i++) {
        int src = __ldg(&g_csr[i]);
        float ee = __expf(lrelu(g_asrc2[src] + ad));
        d += ee;
        float2 v = *(const float2*)(h2base + (size_t)src * HH);
        acc.x += ee * v.x; acc.y += ee * v.y;
    }
    float rd = 1.f / d;
    acc.x *= rd; acc.y *= rd;
    *(float2*)(g_out2 + (size_t)w * HH + lane * 2) = acc;
}

__global__ void final_kernel(const float* __restrict__ b2,
                             const float* __restrict__ Wc1,
                             const float* __restrict__ bc1,
                             const float* __restrict__ Wc2,
                             const float* __restrict__ bc2,
                             float* __restrict__ out, int Nn) {
    __shared__ float sW1[64 * 16], sW2[32], sb1[16], sb2[2], sB2[64];
    int tid = threadIdx.x;
    for (int i = tid; i < 64 * 16; i += blockDim.x) sW1[i] = Wc1[i];
    if (tid < 32) sW2[tid] = Wc2[tid];
    if (tid < 16) sb1[tid] = bc1[tid];
    if (tid < 2)  sb2[tid] = bc2[tid];
    if (tid < 64) sB2[tid] = b2[tid];
    __syncthreads();
    int n = blockIdx.x * blockDim.x + tid;
    if (n >= Nn) return;
    const float* row = g_out2 + (size_t)n * HH;
    float t[16];
#pragma unroll
    for (int j = 0; j < 16; j++) t[j] = sb1[j];
#pragma unroll 8
    for (int i = 0; i < 64; i++) {
        float v = row[i] + sB2[i];
#pragma unroll
        for (int j = 0; j < 16; j++) t[j] += v * sW1[i * 16 + j];
    }
    float o0 = sb2[0], o1 = sb2[1];
#pragma unroll
    for (int j = 0; j < 16; j++) {
        float tj = t[j] > 0.f ? t[j] : 0.f;
        o0 += tj * sW2[j * 2]; o1 += tj * sW2[j * 2 + 1];
    }
    out[n * 2]     = o0;
    out[n * 2 + 1] = o1;
}

extern "C" void kernel_launch(void* const* d_in, const int* in_sizes, int n_in,
                              void* d_out, int out_size) {
    const float* x  = (const float*)d_in[0];
    const int*   ei = (const int*)d_in[1];
    int Nn = in_sizes[0] / FIN;
    int E  = in_sizes[1] / 2;

    int g = -1;
    for (int i = 2; i + 2 < n_in; i++) {
        if (in_sizes[i] == 256 && in_sizes[i + 1] == 256 && in_sizes[i + 2] == FIN * HID2) {
            g = i; break;
        }
    }
    if (g < 0) g = 6;
    const float* gamma  = (const float*)d_in[g + 0];
    const float* beta   = (const float*)d_in[g + 1];
    const float* W1     = (const float*)d_in[g + 2];
    const float* a_src1 = (const float*)d_in[g + 3];
    const float* a_dst1 = (const float*)d_in[g + 4];
    const float* b1     = (const float*)d_in[g + 5];
    const float* W2     = (const float*)d_in[g + 6];
    const float* a_src2 = (const float*)d_in[g + 7];
    const float* a_dst2 = (const float*)d_in[g + 8];
    const float* b2     = (const float*)d_in[g + 9];
    const float* Wc1    = (const float*)d_in[g + 10];
    const float* bc1    = (const float*)d_in[g + 11];
    const float* Wc2    = (const float*)d_in[g + 12];
    const float* bc2    = (const float*)d_in[g + 13];
    float* out = (float*)d_out;

    float *p_h1, *p_h2, *p_c1;
    __nv_bfloat16 *p_xhi, *p_xlo, *p_o1hi, *p_o1lo, *p_w1h, *p_w1l, *p_w2h, *p_w2l;
    cudaGetSymbolAddress((void**)&p_h1,   g_h1);
    cudaGetSymbolAddress((void**)&p_h2,   g_h2);
    cudaGetSymbolAddress((void**)&p_c1,   g_c1);
    cudaGetSymbolAddress((void**)&p_xhi,  g_xhi);
    cudaGetSymbolAddress((void**)&p_xlo,  g_xlo);
    cudaGetSymbolAddress((void**)&p_o1hi, g_o1hi);
    cudaGetSymbolAddress((void**)&p_o1lo, g_o1lo);
    cudaGetSymbolAddress((void**)&p_w1h,  g_W1t_hi);
    cudaGetSymbolAddress((void**)&p_w1l,  g_W1t_lo);
    cudaGetSymbolAddress((void**)&p_w2h,  g_W2t_hi);
    cudaGetSymbolAddress((void**)&p_w2l,  g_W2t_lo);

    int EN = E + Nn;
    int nScanBlocks = (Nn + 255) / 256;

    constexpr int SMEM1 = 4 * (2 * 128 * 24 + 2 * 128 * 24) * 2;  // 98304
    constexpr int SMEM2 = 4 * (2 * 128 * 24 + 2 * 64 * 24) * 2;   // 73728
    cudaFuncSetAttribute((const void*)gemm_bf3<128, 128>,
                         cudaFuncAttributeMaxDynamicSharedMemorySize, SMEM1);
    cudaFuncSetAttribute((const void*)gemm_bf3<128, 64>,
                         cudaFuncAttributeMaxDynamicSharedMemorySize, SMEM2);

    // one-time side stream + events (created on the uncaptured correctness run)
    static cudaStream_t s2 = nullptr;
    static cudaEvent_t evFork = nullptr, evJoin = nullptr;
    if (s2 == nullptr) {
        cudaStreamCreateWithFlags(&s2, cudaStreamNonBlocking);
        cudaEventCreateWithFlags(&evFork, cudaEventDisableTiming);
        cudaEventCreateWithFlags(&evJoin, cudaEventDisableTiming);
    }

    // ---- fork: CSR chain on s2, dense chain on the launch stream ----
    cudaEventRecord(evFork, 0);
    cudaStreamWaitEvent(s2, evFork, 0);

    // chain B (s2): CSR build
    init_cnt<<<(Nn + 255) / 256, 256, 0, s2>>>(Nn);
    hist_kernel<<<(EN + 255) / 256, 256, 0, s2>>>(ei, E, Nn);
    scanA<<<nScanBlocks, 256, 0, s2>>>(Nn);
    scanB<<<1, 256, 0, s2>>>(nScanBlocks);
    scanC<<<(Nn + 255) / 256, 256, 0, s2>>>(Nn, EN);
    fill_kernel<<<(EN + 255) / 256, 256, 0, s2>>>(ei, E, Nn);
    cudaEventRecord(evJoin, s2);

    // chain A (stream 0): BN-stats -> weights -> GEMM1 -> att1
    init_stats<<<1, 256>>>();
    int rowsPerBlock = 128;   // 391 blocks: full occupancy wave (was 196 blocks)
    int nStatBlocks = (Nn + rowsPerBlock - 1) / rowsPerBlock;
    stats_kernel<<<nStatBlocks, 256>>>(x, gamma, beta, Nn, rowsPerBlock, nStatBlocks);
    prep_weights<<<161, 256>>>(W1, W2);
    gemm_bf3<128, 128>
        <<<(Nn + 127) / 128, 256, SMEM1>>>(Nn, HID2, FIN, p_xhi, p_xlo, p_w1h, p_w1l, p_c1, p_h1);
    att1_kernel<<<(Nn * 32 + 255) / 256, 256>>>(a_src1, a_dst1, Nn);

    // ---- join: gather1 needs both chains ----
    cudaStreamWaitEvent(0, evJoin, 0);

    gather1<<<((size_t)Nn * 32 + 255) / 256, 256>>>(b1, Nn);
    gemm_bf3<128, 64>
        <<<(Nn + 127) / 128, 256, SMEM2>>>(Nn, HH, HID2, p_o1hi, p_o1lo, p_w2h, p_w2l, nullptr, p_h2);
    att2_kernel<<<(Nn * 32 + 255) / 256, 256>>>(a_src2, a_dst2, Nn);
    gather2<<<((size_t)Nn * 32 + 255) / 256, 256>>>(Nn);
    final_kernel<<<(Nn + 255) / 256, 256>>>(b2, Wc1, bc1, Wc2, bc2, out, Nn);
}